// round 15
// baseline (speedup 1.0000x reference)
#include <cuda_runtime.h>

// LSEP loss: log1p( sum_i [ exp(-x[i,y_i]) * sum_j exp(x[i,j]) ] - B )
//
// Frozen best structure (R12): balanced 3-row groups, 255 float4 = 8 chunks
// of 32 lanes, 8 front-batched LDG.128 per warp iteration under a 64-reg
// budget (launch_bounds(256,4), GRID=592 = 4 CTAs/SM — the measured-best
// occupancy). pos gathered one group ahead via targets loaded two ahead;
// fp32 hot-loop accumulator; fp64 deterministic tree reduction; fused
// last-block-done finish (self-resetting counter -> graph-replay safe).
//
// R15 change (constants only): the 8 streaming chunk loads use __ldcs
// (evict-first) so the once-read 89MB stream stops thrashing L2; pos/tgt
// keep default caching policy (they ARE re-hit by the stream one iteration
// later).

#define NCLS   340
#define RPG    3               // rows per group
#define C4G    255             // float4s per group (3*85)
#define GRID   592             // 148 SMs * 4 CTAs
#define BLOCK  256
#define WPB    (BLOCK / 32)

__device__ double       g_partials[GRID];
__device__ unsigned int g_count = 0;     // wraps via atomicInc -> replay-safe

__device__ __forceinline__ float exp4(float4 v) {
    return __expf(v.x) + __expf(v.y) + __expf(v.z) + __expf(v.w);
}

__global__ __launch_bounds__(BLOCK, 4)   // 64-reg budget, 4 CTAs/SM
void lsep_grp_kernel(const float* __restrict__ x,
                     const int*   __restrict__ tgt,
                     float*       __restrict__ out,
                     int B)
{
    const int lane   = threadIdx.x & 31;
    const int warp   = threadIdx.x >> 5;
    const int wglob  = blockIdx.x * WPB + warp;
    const int wtotal = GRID * WPB;

    const int nfull = B / RPG;                 // full 3-row groups
    const int rem   = B - nfull * RPG;         // leftover rows (1 for B=65536)

    float acc = 0.0f;

    int p = wglob;
    if (p < nfull) {
        // ---- prologue ----
        const int* tp = tgt + p * RPG;
        int a0 = tp[0], a1 = tp[1], a2 = tp[2];            // targets, group p
        const float* xb = x + (size_t)p * RPG * NCLS;
        float pc0 = __ldg(xb + a0);                        // pos, group p
        float pc1 = __ldg(xb + NCLS + a1);
        float pc2 = __ldg(xb + 2 * NCLS + a2);

        int p1 = p + wtotal;
        int b0 = 0, b1 = 0, b2 = 0;                        // targets, group p+1
        if (p1 < nfull) {
            const int* tn = tgt + p1 * RPG;
            b0 = tn[0]; b1 = tn[1]; b2 = tn[2];
        }

        for (;;) {
            const int pn  = p + wtotal;
            const int pnn = p + 2 * wtotal;
            const bool more = pn < nfull;

            // ---- current group: 8 front-batched STREAMING chunk loads ----
            const float4* g4 = (const float4*)(x + (size_t)p * RPG * NCLS);
            float4 v0 = __ldcs(&g4[lane]);
            float4 v1 = __ldcs(&g4[lane + 32]);
            float4 v2 = __ldcs(&g4[lane + 64]);
            float4 v3 = __ldcs(&g4[lane + 96]);
            float4 v4 = __ldcs(&g4[lane + 128]);
            float4 v5 = __ldcs(&g4[lane + 160]);
            float4 v6 = __ldcs(&g4[lane + 192]);
            float4 v7;
            const bool k7ok = (lane + 224) < C4G;          // lane 31 skips
            if (k7ok) v7 = __ldcs(&g4[lane + 224]);

            // pos gathers for NEXT group (targets resident since last iter)
            float pn0 = 0.f, pn1 = 0.f, pn2 = 0.f;
            if (more) {
                const float* xn = x + (size_t)pn * RPG * NCLS;
                pn0 = __ldg(xn + b0);
                pn1 = __ldg(xn + NCLS + b1);
                pn2 = __ldg(xn + 2 * NCLS + b2);
            }
            // targets for group after next
            int c0 = 0, c1 = 0, c2 = 0;
            if (pnn < nfull) {
                const int* tn = tgt + pnn * RPG;
                c0 = tn[0]; c1 = tn[1]; c2 = tn[2];
            }

            const float e0 = __expf(-pc0);
            const float e1 = __expf(-pc1);
            const float e2 = __expf(-pc2);

            // per-chunk row select: q = lane + 32k (loop-invariant predicates)
            #define EK(k) ((lane + 32*(k)) < 85 ? e0 : \
                           (lane + 32*(k)) < 170 ? e1 : e2)
            acc += EK(0) * exp4(v0);
            acc += EK(1) * exp4(v1);
            acc += EK(2) * exp4(v2);
            acc += EK(3) * exp4(v3);
            acc += EK(4) * exp4(v4);
            acc += EK(5) * exp4(v5);
            acc += EK(6) * exp4(v6);
            if (k7ok) acc += EK(7) * exp4(v7);
            #undef EK

            if (!more) break;
            pc0 = pn0; pc1 = pn1; pc2 = pn2;
            b0 = c0; b1 = c1; b2 = c2;
            p = pn;
        }
    }

    // ---- remainder rows (B % 3): one warp, simple path ----
    if (wglob == 0) {
        for (int r = 0; r < rem; r++) {
            const int row = nfull * RPG + r;
            const float* xr = x + (size_t)row * NCLS;
            const float4* r4 = (const float4*)xr;
            float s = exp4(r4[lane]) + exp4(r4[lane + 32]);
            if (lane < 21) s += exp4(r4[lane + 64]);
            float pos = __ldg(xr + tgt[row]);
            acc += s * __expf(-pos);
        }
    }

    double dacc = (double)acc;                 // one convert per lane

    // ---- block reduction (deterministic) ----
    #pragma unroll
    for (int o = 16; o; o >>= 1)
        dacc += __shfl_xor_sync(0xffffffffu, dacc, o);

    __shared__ double sacc[WPB];
    __shared__ bool   is_last;
    if (lane == 0) sacc[warp] = dacc;
    __syncthreads();

    if (threadIdx.x == 0) {
        double t = 0.0;
        #pragma unroll
        for (int i = 0; i < WPB; i++) t += sacc[i];
        g_partials[blockIdx.x] = t;
        __threadfence();
        unsigned int old = atomicInc(&g_count, GRID - 1);  // wraps to 0
        is_last = (old == GRID - 1);
    }
    __syncthreads();

    // ---- last block: deterministic final reduce + log1p ----
    if (is_last) {
        __threadfence();
        __shared__ double sfin[BLOCK];
        double t = 0.0;
        for (int i = threadIdx.x; i < GRID; i += BLOCK)
            t += g_partials[i];
        sfin[threadIdx.x] = t;
        __syncthreads();
        #pragma unroll
        for (int o = BLOCK / 2; o; o >>= 1) {
            if (threadIdx.x < o) sfin[threadIdx.x] += sfin[threadIdx.x + o];
            __syncthreads();
        }
        if (threadIdx.x == 0)
            out[0] = (float)log1p(sfin[0] - (double)B);
    }
}

extern "C" void kernel_launch(void* const* d_in, const int* in_sizes, int n_in,
                              void* d_out, int out_size)
{
    const float* x   = (const float*)d_in[0];
    const int*   tgt = (const int*)d_in[1];
    float*       out = (float*)d_out;

    int B = in_sizes[0] / NCLS;   // 65536

    lsep_grp_kernel<<<GRID, BLOCK>>>(x, tgt, out, B);
}